// round 1
// baseline (speedup 1.0000x reference)
#include <cuda_runtime.h>
#include <math.h>

// ---------------------------------------------------------------------------
// Problem: two pairwise MLPs + GEMM + sigmoid.
//   hl = X_l @ W0[:5] + b0   (per-entity, [N,128])
//   hr = X_r @ W0[5:]        (per-entity, [N,128])
//   A[l,r] = elu( relu( relu(hl[l]+hr[r]) @ W1 + b1 ) @ Wr + br )
//   out = sigmoid(A_chg @ A_gd), concatenated with A_chg, A_gd.
// ---------------------------------------------------------------------------

#define D_IN 5
#define H0 128
#define H1 64

// scratch: 4 arrays of [1024][128] fp32 (hl_chg, hr_chg, hl_dg, hr_dg)
__device__ float g_hbuf[4 * 1024 * 128];

// ---------------------------------------------------------------------------
// Kernel 1: precompute hl/hr for both branches (tiny)
// a=0: hl_chg = X_ch@Wchg0[:5]+b_chg0 ; a=1: hr_chg = X_g@Wchg0[5:]
// a=2: hl_dg  = X_g @Wdg0[:5]+b_dg0  ; a=3: hr_dg  = X_d@Wdg0[5:]
// ---------------------------------------------------------------------------
__global__ void precompute_kernel(
    const float* __restrict__ X_ch, const float* __restrict__ X_g,
    const float* __restrict__ X_d,
    const float* __restrict__ W_chg0, const float* __restrict__ b_chg0,
    const float* __restrict__ W_dg0,  const float* __restrict__ b_dg0,
    int Nch, int Ng, int Nd)
{
    int a   = blockIdx.y;
    int row = blockIdx.x;
    int k   = threadIdx.x;            // 0..127

    const float* X; const float* W; const float* b = nullptr;
    int rows, woff;
    if (a == 0)      { X = X_ch; W = W_chg0; b = b_chg0; rows = Nch; woff = 0; }
    else if (a == 1) { X = X_g;  W = W_chg0;             rows = Ng;  woff = D_IN; }
    else if (a == 2) { X = X_g;  W = W_dg0;  b = b_dg0;  rows = Ng;  woff = 0; }
    else             { X = X_d;  W = W_dg0;              rows = Nd;  woff = D_IN; }
    if (row >= rows) return;

    float v = b ? b[k] : 0.0f;
#pragma unroll
    for (int d = 0; d < D_IN; d++)
        v = fmaf(X[row * D_IN + d], W[(woff + d) * H0 + k], v);
    g_hbuf[(a * 1024 + row) * H0 + k] = v;
}

// ---------------------------------------------------------------------------
// Kernel 2: pair MLP over a 16x16 tile of (l,r) pairs.
// 256 threads: 64 pair-slots x 4 j-groups.
//   pair-slot p: l = p>>2, r-base = (p&3)*4  (4 pairs per slot)
//   j-group jg : output dims [jg*16, jg*16+16)
// Each thread: acc[4 pairs][16 j] fp32 accumulators (64 regs).
// W1 staged in smem in two 64-k halves (16 KB buffer).
// ---------------------------------------------------------------------------
__global__ __launch_bounds__(256, 2) void pair_mlp_kernel(
    int hl_idx, int hr_idx,
    const float* __restrict__ W1, const float* __restrict__ b1,
    const float* __restrict__ Wr, const float* __restrict__ br,
    float* __restrict__ A, int L, int R)
{
    __shared__ float shl[16][129];   // +1 pad: conflict-free row access
    __shared__ float shr[16][129];
    __shared__ float sw1[64][64];    // half of W1 (k-rows)
    __shared__ float sb1[H1];
    __shared__ float swr[H1];

    const float* g_hl = g_hbuf + hl_idx * 1024 * H0;
    const float* g_hr = g_hbuf + hr_idx * 1024 * H0;

    int t  = threadIdx.x;
    int l0 = blockIdx.y * 16, r0 = blockIdx.x * 16;

    // stage hl/hr tiles (bias already folded into hl)
    for (int i = t; i < 16 * H0; i += 256) {
        int row = i >> 7, col = i & 127;
        shl[row][col] = g_hl[(l0 + row) * H0 + col];
        shr[row][col] = g_hr[(r0 + row) * H0 + col];
    }
    if (t < H1) { sb1[t] = b1[t]; swr[t] = Wr[t]; }

    float acc[4][16];
#pragma unroll
    for (int i = 0; i < 4; i++)
#pragma unroll
        for (int j = 0; j < 16; j++) acc[i][j] = 0.0f;

    const int p  = t >> 2;
    const int jg = t & 3;
    const int l  = p >> 2;
    const int rb = (p & 3) * 4;
    const int j0 = jg * 16;

    for (int kt = 0; kt < 2; kt++) {
        __syncthreads();   // protects sw1 reuse + first-pass tile staging
        for (int i = t; i < 64 * 64; i += 256)
            sw1[i >> 6][i & 63] = W1[(kt * 64 + (i >> 6)) * H1 + (i & 63)];
        __syncthreads();

#pragma unroll 8
        for (int kk = 0; kk < 64; kk++) {
            int k = kt * 64 + kk;
            float hlk = shl[l][k];
            float hv[4];
#pragma unroll
            for (int i = 0; i < 4; i++)
                hv[i] = fmaxf(hlk + shr[rb + i][k], 0.0f);

            float w[16];
#pragma unroll
            for (int c = 0; c < 4; c++) {
                float4 v = *(const float4*)&sw1[kk][j0 + 4 * c];
                w[4 * c + 0] = v.x; w[4 * c + 1] = v.y;
                w[4 * c + 2] = v.z; w[4 * c + 3] = v.w;
            }
#pragma unroll
            for (int i = 0; i < 4; i++)
#pragma unroll
                for (int j = 0; j < 16; j++)
                    acc[i][j] = fmaf(hv[i], w[j], acc[i][j]);
        }
    }

    // epilogue: relu(acc+b1) . Wr, reduce across 4 j-groups, elu, store
    float brv = br[0];
#pragma unroll
    for (int i = 0; i < 4; i++) {
        float s = 0.0f;
#pragma unroll
        for (int j = 0; j < 16; j++) {
            float h2 = fmaxf(acc[i][j] + sb1[j0 + j], 0.0f);
            s = fmaf(h2, swr[j0 + j], s);
        }
        s += __shfl_xor_sync(0xffffffffu, s, 1);
        s += __shfl_xor_sync(0xffffffffu, s, 2);
        if (jg == 0) {
            float x = s + brv;
            float e = (x > 0.0f) ? x : expm1f(x);
            A[(l0 + l) * R + (r0 + rb + i)] = e;
        }
    }
}

// ---------------------------------------------------------------------------
// Kernel 3: C = sigmoid(A @ B), fp32 tiled GEMM (64x64x16, 4x4 per thread)
// ---------------------------------------------------------------------------
__global__ __launch_bounds__(256, 2) void gemm_sigmoid_kernel(
    const float* __restrict__ A, const float* __restrict__ B,
    float* __restrict__ C, int M, int N, int K)
{
    __shared__ float As[16][65];   // A transposed: As[k][m]
    __shared__ float Bs[16][64];

    int t  = threadIdx.x;
    int m0 = blockIdx.y * 64, n0 = blockIdx.x * 64;
    int ty = t >> 4, tx = t & 15;

    float acc[4][4];
#pragma unroll
    for (int i = 0; i < 4; i++)
#pragma unroll
        for (int j = 0; j < 4; j++) acc[i][j] = 0.0f;

    for (int kb = 0; kb < K; kb += 16) {
#pragma unroll
        for (int i = t; i < 1024; i += 256) {
            int r = i >> 4, c = i & 15;
            As[c][r] = A[(m0 + r) * K + kb + c];
        }
#pragma unroll
        for (int i = t; i < 1024; i += 256) {
            int r = i >> 6, c = i & 63;
            Bs[r][c] = B[(kb + r) * N + n0 + c];
        }
        __syncthreads();
#pragma unroll
        for (int k = 0; k < 16; k++) {
            float a[4], b[4];
#pragma unroll
            for (int i = 0; i < 4; i++) a[i] = As[k][ty * 4 + i];
            float4 bv = *(const float4*)&Bs[k][tx * 4];
            b[0] = bv.x; b[1] = bv.y; b[2] = bv.z; b[3] = bv.w;
#pragma unroll
            for (int i = 0; i < 4; i++)
#pragma unroll
                for (int j = 0; j < 4; j++)
                    acc[i][j] = fmaf(a[i], b[j], acc[i][j]);
        }
        __syncthreads();
    }

#pragma unroll
    for (int i = 0; i < 4; i++)
#pragma unroll
        for (int j = 0; j < 4; j++) {
            float v = acc[i][j];
            C[(m0 + ty * 4 + i) * N + (n0 + tx * 4 + j)] =
                1.0f / (1.0f + expf(-v));
        }
}

// ---------------------------------------------------------------------------
// Launch. Inputs (metadata order):
// 0 X_ch, 1 X_g, 2 X_d,
// 3 W_chg0, 4 b_chg0, 5 W_chg1, 6 b_chg1, 7 W_chgr, 8 b_chgr,
// 9 W_dg0, 10 b_dg0, 11 W_dg1, 12 b_dg1, 13 W_dgr, 14 b_dgr
// Output: [sigmoid(A_chd) (Nch*Nd)] [A_chg (Nch*Ng)] [A_gd (Ng*Nd)]
// ---------------------------------------------------------------------------
extern "C" void kernel_launch(void* const* d_in, const int* in_sizes, int n_in,
                              void* d_out, int out_size)
{
    const float* X_ch   = (const float*)d_in[0];
    const float* X_g    = (const float*)d_in[1];
    const float* X_d    = (const float*)d_in[2];
    const float* W_chg0 = (const float*)d_in[3];
    const float* b_chg0 = (const float*)d_in[4];
    const float* W_chg1 = (const float*)d_in[5];
    const float* b_chg1 = (const float*)d_in[6];
    const float* W_chgr = (const float*)d_in[7];
    const float* b_chgr = (const float*)d_in[8];
    const float* W_dg0  = (const float*)d_in[9];
    const float* b_dg0  = (const float*)d_in[10];
    const float* W_dg1  = (const float*)d_in[11];
    const float* b_dg1  = (const float*)d_in[12];
    const float* W_dgr  = (const float*)d_in[13];
    const float* b_dgr  = (const float*)d_in[14];

    int Nch = in_sizes[0] / D_IN;
    int Ng  = in_sizes[1] / D_IN;
    int Nd  = in_sizes[2] / D_IN;

    float* out   = (float*)d_out;
    float* A_chg = out + (size_t)Nch * Nd;
    float* A_gd  = A_chg + (size_t)Nch * Ng;

    // 1) per-entity hl/hr precompute
    int maxN = Nch > Ng ? Nch : Ng; if (Nd > maxN) maxN = Nd;
    precompute_kernel<<<dim3(maxN, 4), 128>>>(
        X_ch, X_g, X_d, W_chg0, b_chg0, W_dg0, b_dg0, Nch, Ng, Nd);

    // 2) pair MLPs
    pair_mlp_kernel<<<dim3(Ng / 16, Nch / 16), 256>>>(
        0, 1, W_chg1, b_chg1, W_chgr, b_chgr, A_chg, Nch, Ng);
    pair_mlp_kernel<<<dim3(Nd / 16, Ng / 16), 256>>>(
        2, 3, W_dg1, b_dg1, W_dgr, b_dgr, A_gd, Ng, Nd);

    // 3) A_chd = A_chg @ A_gd, sigmoid
    gemm_sigmoid_kernel<<<dim3(Nd / 64, Nch / 64), 256>>>(
        A_chg, A_gd, out, Nch, Nd, Ng);
}

// round 2
// speedup vs baseline: 1.0029x; 1.0029x over previous
#include <cuda_runtime.h>
#include <math.h>

#define D_IN 5
#define H0 128
#define H1 64

// scratch: 4 arrays of [1024][128] fp32 (hl_chg, hr_chg, hl_dg, hr_dg)
__device__ float g_hbuf[4 * 1024 * 128];

typedef unsigned long long u64;

__device__ __forceinline__ u64 pack2(float lo, float hi) {
    u64 r;
    asm("mov.b64 %0, {%1, %2};" : "=l"(r) : "f"(lo), "f"(hi));
    return r;
}
__device__ __forceinline__ void unpack2(u64 v, float& lo, float& hi) {
    asm("mov.b64 {%0, %1}, %2;" : "=f"(lo), "=f"(hi) : "l"(v));
}
__device__ __forceinline__ void ffma2(u64& d, u64 a, u64 b) {
    asm("fma.rn.f32x2 %0, %1, %2, %3;" : "=l"(d) : "l"(a), "l"(b), "l"(d));
}

// ---------------------------------------------------------------------------
// Kernel 1: precompute hl/hr for both branches (tiny)
// ---------------------------------------------------------------------------
__global__ void precompute_kernel(
    const float* __restrict__ X_ch, const float* __restrict__ X_g,
    const float* __restrict__ X_d,
    const float* __restrict__ W_chg0, const float* __restrict__ b_chg0,
    const float* __restrict__ W_dg0,  const float* __restrict__ b_dg0,
    int Nch, int Ng, int Nd)
{
    int a   = blockIdx.y;
    int row = blockIdx.x;
    int k   = threadIdx.x;            // 0..127

    const float* X; const float* W; const float* b = nullptr;
    int rows, woff;
    if (a == 0)      { X = X_ch; W = W_chg0; b = b_chg0; rows = Nch; woff = 0; }
    else if (a == 1) { X = X_g;  W = W_chg0;             rows = Ng;  woff = D_IN; }
    else if (a == 2) { X = X_g;  W = W_dg0;  b = b_dg0;  rows = Ng;  woff = 0; }
    else             { X = X_d;  W = W_dg0;              rows = Nd;  woff = D_IN; }
    if (row >= rows) return;

    float v = b ? b[k] : 0.0f;
#pragma unroll
    for (int d = 0; d < D_IN; d++)
        v = fmaf(X[row * D_IN + d], W[(woff + d) * H0 + k], v);
    g_hbuf[(a * 1024 + row) * H0 + k] = v;
}

// ---------------------------------------------------------------------------
// Kernel 2: pair MLP, 16x16 pair tile, packed f32x2 accumulators.
// 256 threads: 64 pair-slots x 4 j-groups.
//   pair-slot p: l = p>>2, r-base = (p&3)*4  (4 pairs per slot)
//   j-group jg : output dims [jg*16, jg*16+16) as 8 packed f32x2
// ---------------------------------------------------------------------------
__global__ __launch_bounds__(256, 2) void pair_mlp_kernel(
    int hl_idx, int hr_idx,
    const float* __restrict__ W1, const float* __restrict__ b1,
    const float* __restrict__ Wr, const float* __restrict__ br,
    float* __restrict__ A, int L, int R)
{
    __shared__ float shl[16][129];   // +1 pad: conflict-free row access
    __shared__ float shr[16][129];
    __shared__ float sw1[64][64];    // half of W1 (k-rows); rows 256B aligned
    __shared__ float sb1[H1];
    __shared__ float swr[H1];

    const float* g_hl = g_hbuf + hl_idx * 1024 * H0;
    const float* g_hr = g_hbuf + hr_idx * 1024 * H0;

    int t  = threadIdx.x;
    int l0 = blockIdx.y * 16, r0 = blockIdx.x * 16;

    for (int i = t; i < 16 * H0; i += 256) {
        int row = i >> 7, col = i & 127;
        shl[row][col] = g_hl[(l0 + row) * H0 + col];
        shr[row][col] = g_hr[(r0 + row) * H0 + col];
    }
    if (t < H1) { sb1[t] = b1[t]; swr[t] = Wr[t]; }

    u64 acc2[4][8];
#pragma unroll
    for (int i = 0; i < 4; i++)
#pragma unroll
        for (int c = 0; c < 8; c++) acc2[i][c] = 0ull;

    const int p  = t >> 2;
    const int jg = t & 3;
    const int l  = p >> 2;
    const int rb = (p & 3) * 4;
    const int j0 = jg * 16;

    for (int kt = 0; kt < 2; kt++) {
        __syncthreads();   // protects sw1 reuse + first-pass tile staging
        for (int i = t; i < 64 * 64; i += 256)
            sw1[i >> 6][i & 63] = W1[(kt * 64 + (i >> 6)) * H1 + (i & 63)];
        __syncthreads();

#pragma unroll 8
        for (int kk = 0; kk < 64; kk++) {
            int k = kt * 64 + kk;
            float hlk = shl[l][k];
            u64 hv2[4];
#pragma unroll
            for (int i = 0; i < 4; i++) {
                float h = fmaxf(hlk + shr[rb + i][k], 0.0f);
                hv2[i] = pack2(h, h);
            }

            u64 w2[8];
            const ulonglong2* wp = (const ulonglong2*)&sw1[kk][j0];
#pragma unroll
            for (int c = 0; c < 4; c++) {
                ulonglong2 v = wp[c];
                w2[2 * c]     = v.x;
                w2[2 * c + 1] = v.y;
            }
#pragma unroll
            for (int i = 0; i < 4; i++)
#pragma unroll
                for (int c = 0; c < 8; c++)
                    ffma2(acc2[i][c], hv2[i], w2[c]);
        }
    }

    // epilogue: relu(acc+b1) . Wr, reduce across 4 j-groups, elu, store
    float brv = br[0];
#pragma unroll
    for (int i = 0; i < 4; i++) {
        float s = 0.0f;
#pragma unroll
        for (int c = 0; c < 8; c++) {
            float lo, hi;
            unpack2(acc2[i][c], lo, hi);
            float h2a = fmaxf(lo + sb1[j0 + 2 * c],     0.0f);
            float h2b = fmaxf(hi + sb1[j0 + 2 * c + 1], 0.0f);
            s = fmaf(h2a, swr[j0 + 2 * c],     s);
            s = fmaf(h2b, swr[j0 + 2 * c + 1], s);
        }
        s += __shfl_xor_sync(0xffffffffu, s, 1);
        s += __shfl_xor_sync(0xffffffffu, s, 2);
        if (jg == 0) {
            float x = s + brv;
            float e = (x > 0.0f) ? x : expm1f(x);
            A[(l0 + l) * R + (r0 + rb + i)] = e;
        }
    }
}

// ---------------------------------------------------------------------------
// Kernel 3: C = sigmoid(A @ B), fp32 tiled GEMM (64x64x16), packed f32x2,
// vectorized LDS (1x LDS.128 per operand fragment).
// ---------------------------------------------------------------------------
__global__ __launch_bounds__(256, 2) void gemm_sigmoid_kernel(
    const float* __restrict__ A, const float* __restrict__ B,
    float* __restrict__ C, int M, int N, int K)
{
    __shared__ float As[16][68];   // A transposed: As[k][m]; rows 272B (16B-aligned)
    __shared__ float Bs[16][64];

    int t  = threadIdx.x;
    int m0 = blockIdx.y * 64, n0 = blockIdx.x * 64;
    int ty = t >> 4, tx = t & 15;

    u64 acc2[4][2];
#pragma unroll
    for (int i = 0; i < 4; i++) { acc2[i][0] = 0ull; acc2[i][1] = 0ull; }

    for (int kb = 0; kb < K; kb += 16) {
#pragma unroll
        for (int i = t; i < 1024; i += 256) {
            int r = i >> 4, c = i & 15;
            As[c][r] = A[(m0 + r) * K + kb + c];
        }
#pragma unroll
        for (int i = t; i < 1024; i += 256) {
            int r = i >> 6, c = i & 63;
            Bs[r][c] = B[(kb + r) * N + n0 + c];
        }
        __syncthreads();
#pragma unroll
        for (int k = 0; k < 16; k++) {
            float4 av = *(const float4*)&As[k][ty * 4];
            ulonglong2 bv = *(const ulonglong2*)&Bs[k][tx * 4];
            u64 a2[4];
            a2[0] = pack2(av.x, av.x);
            a2[1] = pack2(av.y, av.y);
            a2[2] = pack2(av.z, av.z);
            a2[3] = pack2(av.w, av.w);
#pragma unroll
            for (int i = 0; i < 4; i++) {
                ffma2(acc2[i][0], a2[i], bv.x);
                ffma2(acc2[i][1], a2[i], bv.y);
            }
        }
        __syncthreads();
    }

#pragma unroll
    for (int i = 0; i < 4; i++) {
        float v0, v1, v2, v3;
        unpack2(acc2[i][0], v0, v1);
        unpack2(acc2[i][1], v2, v3);
        float* row = &C[(m0 + ty * 4 + i) * N + (n0 + tx * 4)];
        row[0] = 1.0f / (1.0f + expf(-v0));
        row[1] = 1.0f / (1.0f + expf(-v1));
        row[2] = 1.0f / (1.0f + expf(-v2));
        row[3] = 1.0f / (1.0f + expf(-v3));
    }
}

// ---------------------------------------------------------------------------
// Launch
// ---------------------------------------------------------------------------
extern "C" void kernel_launch(void* const* d_in, const int* in_sizes, int n_in,
                              void* d_out, int out_size)
{
    const float* X_ch   = (const float*)d_in[0];
    const float* X_g    = (const float*)d_in[1];
    const float* X_d    = (const float*)d_in[2];
    const float* W_chg0 = (const float*)d_in[3];
    const float* b_chg0 = (const float*)d_in[4];
    const float* W_chg1 = (const float*)d_in[5];
    const float* b_chg1 = (const float*)d_in[6];
    const float* W_chgr = (const float*)d_in[7];
    const float* b_chgr = (const float*)d_in[8];
    const float* W_dg0  = (const float*)d_in[9];
    const float* b_dg0  = (const float*)d_in[10];
    const float* W_dg1  = (const float*)d_in[11];
    const float* b_dg1  = (const float*)d_in[12];
    const float* W_dgr  = (const float*)d_in[13];
    const float* b_dgr  = (const float*)d_in[14];

    int Nch = in_sizes[0] / D_IN;
    int Ng  = in_sizes[1] / D_IN;
    int Nd  = in_sizes[2] / D_IN;

    float* out   = (float*)d_out;
    float* A_chg = out + (size_t)Nch * Nd;
    float* A_gd  = A_chg + (size_t)Nch * Ng;

    int maxN = Nch > Ng ? Nch : Ng; if (Nd > maxN) maxN = Nd;
    precompute_kernel<<<dim3(maxN, 4), 128>>>(
        X_ch, X_g, X_d, W_chg0, b_chg0, W_dg0, b_dg0, Nch, Ng, Nd);

    pair_mlp_kernel<<<dim3(Ng / 16, Nch / 16), 256>>>(
        0, 1, W_chg1, b_chg1, W_chgr, b_chgr, A_chg, Nch, Ng);
    pair_mlp_kernel<<<dim3(Nd / 16, Ng / 16), 256>>>(
        2, 3, W_dg1, b_dg1, W_dgr, b_dgr, A_gd, Ng, Nd);

    gemm_sigmoid_kernel<<<dim3(Nd / 64, Nch / 64), 256>>>(
        A_chg, A_gd, out, Nch, Nd, Ng);
}

// round 4
// speedup vs baseline: 3.0452x; 3.0365x over previous
#include <cuda_runtime.h>
#include <cuda_bf16.h>
#include <math.h>
#include <stdint.h>

#define D_IN 5
#define H0 128
#define H1 64

// scratch: 4 arrays of [1024][128] fp32 (hl_chg, hr_chg, hl_dg, hr_dg)
__device__ float g_hbuf[4 * 1024 * 128];
// W1 hi/lo bf16, n-major padded: [branch][hi/lo][64 rows][136 cols]
__device__ __align__(16) __nv_bfloat16 g_w1[2][2][64 * 136];

// ---------------------------------------------------------------------------
// mma.sync m16n8k16 row.col f32.bf16.bf16.f32 (sm_80+, works on plain sm_103)
// ---------------------------------------------------------------------------
__device__ __forceinline__ void mma_bf16(
    float& d0, float& d1, float& d2, float& d3,
    uint32_t a0, uint32_t a1, uint32_t a2, uint32_t a3,
    uint32_t b0, uint32_t b1)
{
    asm volatile(
        "mma.sync.aligned.m16n8k16.row.col.f32.bf16.bf16.f32 "
        "{%0,%1,%2,%3}, {%4,%5,%6,%7}, {%8,%9}, {%0,%1,%2,%3};"
        : "+f"(d0), "+f"(d1), "+f"(d2), "+f"(d3)
        : "r"(a0), "r"(a1), "r"(a2), "r"(a3), "r"(b0), "r"(b1));
}

// split (a,b) -> packed bf16x2 hi and lo (lo = residual)
__device__ __forceinline__ void split2(float a, float b, uint32_t& hi, uint32_t& lo) {
    __nv_bfloat162 h = __float22bfloat162_rn(make_float2(a, b));
    float ra = a - __bfloat162float(h.x);
    float rb = b - __bfloat162float(h.y);
    __nv_bfloat162 l = __float22bfloat162_rn(make_float2(ra, rb));
    hi = *reinterpret_cast<uint32_t*>(&h);
    lo = *reinterpret_cast<uint32_t*>(&l);
}

// ---------------------------------------------------------------------------
// Kernel 1: precompute hl/hr for both branches (bias folded into hl)
// ---------------------------------------------------------------------------
__global__ void precompute_kernel(
    const float* __restrict__ X_ch, const float* __restrict__ X_g,
    const float* __restrict__ X_d,
    const float* __restrict__ W_chg0, const float* __restrict__ b_chg0,
    const float* __restrict__ W_dg0,  const float* __restrict__ b_dg0,
    int Nch, int Ng, int Nd)
{
    int a   = blockIdx.y;
    int row = blockIdx.x;
    int k   = threadIdx.x;

    const float* X; const float* W; const float* b = nullptr;
    int rows, woff;
    if (a == 0)      { X = X_ch; W = W_chg0; b = b_chg0; rows = Nch; woff = 0; }
    else if (a == 1) { X = X_g;  W = W_chg0;             rows = Ng;  woff = D_IN; }
    else if (a == 2) { X = X_g;  W = W_dg0;  b = b_dg0;  rows = Ng;  woff = 0; }
    else             { X = X_d;  W = W_dg0;              rows = Nd;  woff = D_IN; }
    if (row >= rows) return;

    float v = b ? b[k] : 0.0f;
#pragma unroll
    for (int d = 0; d < D_IN; d++)
        v = fmaf(X[row * D_IN + d], W[(woff + d) * H0 + k], v);
    g_hbuf[(a * 1024 + row) * H0 + k] = v;
}

// ---------------------------------------------------------------------------
// Kernel 1b: split W1 (both branches) into bf16 hi/lo, n-major padded [64][136]
// ---------------------------------------------------------------------------
__global__ void w1split_kernel(const float* __restrict__ W1a,
                               const float* __restrict__ W1b)
{
    int br = blockIdx.x;
    const float* W = br ? W1b : W1a;
    for (int i = threadIdx.x; i < 64 * 136; i += blockDim.x) {
        int n = i / 136, k = i % 136;
        float v = (k < H0) ? W[k * H1 + n] : 0.0f;
        __nv_bfloat16 h = __float2bfloat16(v);
        __nv_bfloat16 l = __float2bfloat16(v - __bfloat162float(h));
        g_w1[br][0][i] = h;
        g_w1[br][1][i] = l;
    }
}

// ---------------------------------------------------------------------------
// Kernel 2: pair MLP with warp-level bf16 MMA (3-product split).
// CTA = 128 threads (4 warps). Warp w owns l = l0+w; CTA covers 128 r's in
// 4 iterations of 32 pairs (two m16 halves sharing B fragments).
// smem layout (bytes):
//   [0,17408)      W1 hi  bf16 [64][136]
//   [17408,34816)  W1 lo  bf16 [64][136]
//   [34816,52224)  shr    f32  [32][136]  (per-iteration r tile)
//   [52224,54272)  shl    f32  [4][128]
//   [54272,54528)  b1     f32  [64]
//   [54528,54784)  wr     f32  [64]
// ---------------------------------------------------------------------------
#define SMEM_PAIR 54784

__global__ __launch_bounds__(128) void pair_mlp_mma(
    int hl_idx, int hr_idx, int branch,
    const float* __restrict__ b1, const float* __restrict__ Wr,
    const float* __restrict__ br,
    float* __restrict__ A, int R)
{
    extern __shared__ char smem[];
    __nv_bfloat16* sw1hi = (__nv_bfloat16*)smem;
    __nv_bfloat16* sw1lo = (__nv_bfloat16*)(smem + 17408);
    float* shr = (float*)(smem + 34816);
    float* shl = (float*)(smem + 52224);
    float* sb1 = (float*)(smem + 54272);
    float* swr = (float*)(smem + 54528);
    const uint32_t* w1hi32 = (const uint32_t*)sw1hi;
    const uint32_t* w1lo32 = (const uint32_t*)sw1lo;

    const float* g_hl = g_hbuf + hl_idx * 1024 * H0;
    const float* g_hr = g_hbuf + hr_idx * 1024 * H0;

    const int t    = threadIdx.x;
    const int wid  = t >> 5;
    const int lane = t & 31;
    const int l0   = blockIdx.y * 4;
    const int rblk = blockIdx.x * 128;

    // ---- stage W1 hi/lo (uint4 copies), shl, b1, wr ----
    {
        const uint4* ghi = (const uint4*)g_w1[branch][0];
        const uint4* glo = (const uint4*)g_w1[branch][1];
        uint4* shi = (uint4*)sw1hi;
        uint4* slo = (uint4*)sw1lo;
        for (int i = t; i < 1088; i += 128) { shi[i] = ghi[i]; slo[i] = glo[i]; }
    }
    ((float4*)shl)[t] = ((const float4*)(g_hl + (size_t)l0 * H0))[t];
    if (t < H1) { sb1[t] = b1[t]; swr[t] = Wr[t]; }

    const float* shl_l = shl + wid * H0;
    const float brv = br[0];

    for (int riter = 0; riter < 4; riter++) {
        const int rbase = rblk + riter * 32;

        // ---- stage shr [32][136] ----
        __syncthreads();
        for (int i = t; i < 1024; i += 128) {
            int row = i >> 5, c4 = i & 31;
            float4 v = ((const float4*)(g_hr + (size_t)(rbase + row) * H0))[c4];
            *(float4*)(shr + row * 136 + c4 * 4) = v;
        }
        __syncthreads();

        float acc[2][8][4];
#pragma unroll
        for (int mh = 0; mh < 2; mh++)
#pragma unroll
            for (int nt = 0; nt < 8; nt++)
#pragma unroll
                for (int c = 0; c < 4; c++) acc[mh][nt][c] = 0.0f;

        const int kq = (lane & 3) * 2;   // k offset within k-tile (col pair)
        const int rq = lane >> 2;        // row offset within m8 group / n within n-tile

#pragma unroll
        for (int kt = 0; kt < 8; kt++) {
            const int kk = kt * 16 + kq;

            // ---- B fragments (8 n-tiles, hi+lo) ----
            uint32_t bhi[8][2], blo[8][2];
#pragma unroll
            for (int nt = 0; nt < 8; nt++) {
                int w0 = (nt * 8 + rq) * 68 + kt * 8 + (lane & 3);
                bhi[nt][0] = w1hi32[w0];
                bhi[nt][1] = w1hi32[w0 + 4];
                blo[nt][0] = w1lo32[w0];
                blo[nt][1] = w1lo32[w0 + 4];
            }

            // ---- A fragments (2 m16 halves, hi+lo) ----
            uint32_t ahi[2][4], alo[2][4];
            float2 y0 = *(const float2*)(shl_l + kk);
            float2 y1 = *(const float2*)(shl_l + kk + 8);
#pragma unroll
            for (int mh = 0; mh < 2; mh++) {
                int r_lo = mh * 16 + rq;
                const float* p0 = shr + r_lo * 136 + kk;
                const float* p1 = shr + (r_lo + 8) * 136 + kk;
                float2 x00 = *(const float2*)p0;        // (r, k0)
                float2 x01 = *(const float2*)(p0 + 8);  // (r, k0+8)
                float2 x10 = *(const float2*)p1;        // (r+8, k0)
                float2 x11 = *(const float2*)(p1 + 8);  // (r+8, k0+8)
                split2(fmaxf(x00.x + y0.x, 0.f), fmaxf(x00.y + y0.y, 0.f),
                       ahi[mh][0], alo[mh][0]);
                split2(fmaxf(x10.x + y0.x, 0.f), fmaxf(x10.y + y0.y, 0.f),
                       ahi[mh][1], alo[mh][1]);
                split2(fmaxf(x01.x + y1.x, 0.f), fmaxf(x01.y + y1.y, 0.f),
                       ahi[mh][2], alo[mh][2]);
                split2(fmaxf(x11.x + y1.x, 0.f), fmaxf(x11.y + y1.y, 0.f),
                       ahi[mh][3], alo[mh][3]);
            }

            // ---- 3-product MMAs ----
#pragma unroll
            for (int mh = 0; mh < 2; mh++)
#pragma unroll
                for (int nt = 0; nt < 8; nt++) {
                    mma_bf16(acc[mh][nt][0], acc[mh][nt][1],
                             acc[mh][nt][2], acc[mh][nt][3],
                             ahi[mh][0], ahi[mh][1], ahi[mh][2], ahi[mh][3],
                             bhi[nt][0], bhi[nt][1]);
                    mma_bf16(acc[mh][nt][0], acc[mh][nt][1],
                             acc[mh][nt][2], acc[mh][nt][3],
                             ahi[mh][0], ahi[mh][1], ahi[mh][2], ahi[mh][3],
                             blo[nt][0], blo[nt][1]);
                    mma_bf16(acc[mh][nt][0], acc[mh][nt][1],
                             acc[mh][nt][2], acc[mh][nt][3],
                             alo[mh][0], alo[mh][1], alo[mh][2], alo[mh][3],
                             bhi[nt][0], bhi[nt][1]);
                }
        }

        // ---- epilogue: layer-2 relu/dot(Wr), quad reduce, ELU, store ----
#pragma unroll
        for (int mh = 0; mh < 2; mh++) {
            float s0 = 0.0f, s1 = 0.0f;
#pragma unroll
            for (int nt = 0; nt < 8; nt++) {
                int j0 = nt * 8 + kq;
                float bb0 = sb1[j0], bb1 = sb1[j0 + 1];
                float ww0 = swr[j0], ww1 = swr[j0 + 1];
                s0 = fmaf(fmaxf(acc[mh][nt][0] + bb0, 0.f), ww0, s0);
                s0 = fmaf(fmaxf(acc[mh][nt][1] + bb1, 0.f), ww1, s0);
                s1 = fmaf(fmaxf(acc[mh][nt][2] + bb0, 0.f), ww0, s1);
                s1 = fmaf(fmaxf(acc[mh][nt][3] + bb1, 0.f), ww1, s1);
            }
            s0 += __shfl_xor_sync(0xffffffffu, s0, 1);
            s0 += __shfl_xor_sync(0xffffffffu, s0, 2);
            s1 += __shfl_xor_sync(0xffffffffu, s1, 1);
            s1 += __shfl_xor_sync(0xffffffffu, s1, 2);
            if ((lane & 3) == 0) {
                int r_lo = rbase + mh * 16 + rq;
                float x0 = s0 + brv;
                float x1 = s1 + brv;
                float e0 = (x0 > 0.0f) ? x0 : expm1f(x0);
                float e1 = (x1 > 0.0f) ? x1 : expm1f(x1);
                float* arow = A + (size_t)(l0 + wid) * R;
                arow[r_lo]     = e0;
                arow[r_lo + 8] = e1;
            }
        }
    }
}

// ---------------------------------------------------------------------------
// Kernel 3: C = sigmoid(A @ B), fp32 tiled GEMM (64x64x16, 4x4/thread)
// ---------------------------------------------------------------------------
__global__ __launch_bounds__(256, 2) void gemm_sigmoid_kernel(
    const float* __restrict__ A, const float* __restrict__ B,
    float* __restrict__ C, int M, int N, int K)
{
    __shared__ float As[16][68];
    __shared__ float Bs[16][64];

    int t  = threadIdx.x;
    int m0 = blockIdx.y * 64, n0 = blockIdx.x * 64;
    int ty = t >> 4, tx = t & 15;

    float acc[4][4];
#pragma unroll
    for (int i = 0; i < 4; i++)
#pragma unroll
        for (int j = 0; j < 4; j++) acc[i][j] = 0.0f;

    for (int kb = 0; kb < K; kb += 16) {
#pragma unroll
        for (int i = t; i < 1024; i += 256) {
            int r = i >> 4, c = i & 15;
            As[c][r] = A[(m0 + r) * K + kb + c];
        }
#pragma unroll
        for (int i = t; i < 1024; i += 256) {
            int r = i >> 6, c = i & 63;
            Bs[r][c] = B[(kb + r) * N + n0 + c];
        }
        __syncthreads();
#pragma unroll
        for (int k = 0; k < 16; k++) {
            float4 av = *(const float4*)&As[k][ty * 4];
            float4 bv = *(const float4*)&Bs[k][tx * 4];
            float a[4] = { av.x, av.y, av.z, av.w };
            float b[4] = { bv.x, bv.y, bv.z, bv.w };
#pragma unroll
            for (int i = 0; i < 4; i++)
#pragma unroll
                for (int j = 0; j < 4; j++)
                    acc[i][j] = fmaf(a[i], b[j], acc[i][j]);
        }
        __syncthreads();
    }

#pragma unroll
    for (int i = 0; i < 4; i++)
#pragma unroll
        for (int j = 0; j < 4; j++) {
            float v = acc[i][j];
            C[(m0 + ty * 4 + i) * N + (n0 + tx * 4 + j)] =
                1.0f / (1.0f + expf(-v));
        }
}

// ---------------------------------------------------------------------------
// Launch
// ---------------------------------------------------------------------------
extern "C" void kernel_launch(void* const* d_in, const int* in_sizes, int n_in,
                              void* d_out, int out_size)
{
    const float* X_ch   = (const float*)d_in[0];
    const float* X_g    = (const float*)d_in[1];
    const float* X_d    = (const float*)d_in[2];
    const float* W_chg0 = (const float*)d_in[3];
    const float* b_chg0 = (const float*)d_in[4];
    const float* W_chg1 = (const float*)d_in[5];
    const float* b_chg1 = (const float*)d_in[6];
    const float* W_chgr = (const float*)d_in[7];
    const float* b_chgr = (const float*)d_in[8];
    const float* W_dg0  = (const float*)d_in[9];
    const float* b_dg0  = (const float*)d_in[10];
    const float* W_dg1  = (const float*)d_in[11];
    const float* b_dg1  = (const float*)d_in[12];
    const float* W_dgr  = (const float*)d_in[13];
    const float* b_dgr  = (const float*)d_in[14];

    int Nch = in_sizes[0] / D_IN;
    int Ng  = in_sizes[1] / D_IN;
    int Nd  = in_sizes[2] / D_IN;

    float* out   = (float*)d_out;
    float* A_chg = out + (size_t)Nch * Nd;
    float* A_gd  = A_chg + (size_t)Nch * Ng;

    int maxN = Nch > Ng ? Nch : Ng; if (Nd > maxN) maxN = Nd;
    precompute_kernel<<<dim3(maxN, 4), 128>>>(
        X_ch, X_g, X_d, W_chg0, b_chg0, W_dg0, b_dg0, Nch, Ng, Nd);
    w1split_kernel<<<2, 256>>>(W_chg1, W_dg1);

    cudaFuncSetAttribute(pair_mlp_mma,
                         cudaFuncAttributeMaxDynamicSharedMemorySize, SMEM_PAIR);

    pair_mlp_mma<<<dim3(Ng / 128, Nch / 4), 128, SMEM_PAIR>>>(
        0, 1, 0, b_chg1, W_chgr, b_chgr, A_chg, Ng);
    pair_mlp_mma<<<dim3(Nd / 128, Ng / 4), 128, SMEM_PAIR>>>(
        2, 3, 1, b_dg1, W_dgr, b_dgr, A_gd, Nd);

    gemm_sigmoid_kernel<<<dim3(Nd / 64, Nch / 64), 256>>>(
        A_chg, A_gd, out, Nch, Nd, Ng);
}

// round 5
// speedup vs baseline: 3.0764x; 1.0103x over previous
#include <cuda_runtime.h>
#include <cuda_bf16.h>
#include <math.h>
#include <stdint.h>

#define D_IN 5
#define H0 128
#define H1 64

// scratch: 4 arrays of [1024][128] fp32 (hl_chg, hr_chg, hl_dg, hr_dg)
__device__ float g_hbuf[4 * 1024 * 128];
// W1 hi/lo bf16, n-major padded: [branch][hi/lo][64 rows][136 cols]
__device__ __align__(16) __nv_bfloat16 g_w1[2][2][64 * 136];

// ---------------------------------------------------------------------------
// mma.sync m16n8k16 row.col f32.bf16.bf16.f32
// ---------------------------------------------------------------------------
__device__ __forceinline__ void mma_bf16(
    float& d0, float& d1, float& d2, float& d3,
    uint32_t a0, uint32_t a1, uint32_t a2, uint32_t a3,
    uint32_t b0, uint32_t b1)
{
    asm volatile(
        "mma.sync.aligned.m16n8k16.row.col.f32.bf16.bf16.f32 "
        "{%0,%1,%2,%3}, {%4,%5,%6,%7}, {%8,%9}, {%0,%1,%2,%3};"
        : "+f"(d0), "+f"(d1), "+f"(d2), "+f"(d3)
        : "r"(a0), "r"(a1), "r"(a2), "r"(a3), "r"(b0), "r"(b1));
}

// split (a,b) -> packed bf16x2 hi and lo (lo = residual)
__device__ __forceinline__ void split2(float a, float b, uint32_t& hi, uint32_t& lo) {
    __nv_bfloat162 h = __float22bfloat162_rn(make_float2(a, b));
    float ra = a - __bfloat162float(h.x);
    float rb = b - __bfloat162float(h.y);
    __nv_bfloat162 l = __float22bfloat162_rn(make_float2(ra, rb));
    hi = *reinterpret_cast<uint32_t*>(&h);
    lo = *reinterpret_cast<uint32_t*>(&l);
}

// ---------------------------------------------------------------------------
// Kernel 1: precompute hl/hr for both branches (bias folded into hl)
// ---------------------------------------------------------------------------
__global__ void precompute_kernel(
    const float* __restrict__ X_ch, const float* __restrict__ X_g,
    const float* __restrict__ X_d,
    const float* __restrict__ W_chg0, const float* __restrict__ b_chg0,
    const float* __restrict__ W_dg0,  const float* __restrict__ b_dg0,
    int Nch, int Ng, int Nd)
{
    int a   = blockIdx.y;
    int row = blockIdx.x;
    int k   = threadIdx.x;

    const float* X; const float* W; const float* b = nullptr;
    int rows, woff;
    if (a == 0)      { X = X_ch; W = W_chg0; b = b_chg0; rows = Nch; woff = 0; }
    else if (a == 1) { X = X_g;  W = W_chg0;             rows = Ng;  woff = D_IN; }
    else if (a == 2) { X = X_g;  W = W_dg0;  b = b_dg0;  rows = Ng;  woff = 0; }
    else             { X = X_d;  W = W_dg0;              rows = Nd;  woff = D_IN; }
    if (row >= rows) return;

    float v = b ? b[k] : 0.0f;
#pragma unroll
    for (int d = 0; d < D_IN; d++)
        v = fmaf(X[row * D_IN + d], W[(woff + d) * H0 + k], v);
    g_hbuf[(a * 1024 + row) * H0 + k] = v;
}

// ---------------------------------------------------------------------------
// Kernel 1b: split W1 (both branches) into bf16 hi/lo, n-major padded [64][136]
// ---------------------------------------------------------------------------
__global__ void w1split_kernel(const float* __restrict__ W1a,
                               const float* __restrict__ W1b)
{
    int br = blockIdx.x;
    const float* W = br ? W1b : W1a;
    for (int i = threadIdx.x; i < 64 * 136; i += blockDim.x) {
        int n = i / 136, k = i % 136;
        float v = (k < H0) ? W[k * H1 + n] : 0.0f;
        __nv_bfloat16 h = __float2bfloat16(v);
        __nv_bfloat16 l = __float2bfloat16(v - __bfloat162float(h));
        g_w1[br][0][i] = h;
        g_w1[br][1][i] = l;
    }
}

// ---------------------------------------------------------------------------
// Kernel 2: pair MLP with warp-level bf16 MMA (3-product split), both branches
// in one grid (blockIdx.z). CTA = 128 threads (4 warps), warp w owns l=l0+w,
// CTA covers 128 r's in 4 iterations of 32.
// ---------------------------------------------------------------------------
#define SMEM_PAIR 54784

__global__ __launch_bounds__(128, 4) void pair_mlp_mma(
    const float* __restrict__ b1a, const float* __restrict__ Wra,
    const float* __restrict__ bra, float* __restrict__ Aa,
    const float* __restrict__ b1b, const float* __restrict__ Wrb,
    const float* __restrict__ brb, float* __restrict__ Ab,
    int R)
{
    extern __shared__ char smem[];
    __nv_bfloat16* sw1hi = (__nv_bfloat16*)smem;
    __nv_bfloat16* sw1lo = (__nv_bfloat16*)(smem + 17408);
    float* shr = (float*)(smem + 34816);
    float* shl = (float*)(smem + 52224);
    float* sb1 = (float*)(smem + 54272);
    float* swr = (float*)(smem + 54528);
    const uint32_t* w1hi32 = (const uint32_t*)sw1hi;
    const uint32_t* w1lo32 = (const uint32_t*)sw1lo;

    const int branch = blockIdx.z;
    const float* g_hl = g_hbuf + (branch ? 2 : 0) * 1024 * H0;
    const float* g_hr = g_hbuf + (branch ? 3 : 1) * 1024 * H0;
    const float* b1 = branch ? b1b : b1a;
    const float* Wr = branch ? Wrb : Wra;
    const float* br = branch ? brb : bra;
    float* A = branch ? Ab : Aa;

    const int t    = threadIdx.x;
    const int wid  = t >> 5;
    const int lane = t & 31;
    const int l0   = blockIdx.y * 4;
    const int rblk = blockIdx.x * 128;

    // ---- stage W1 hi/lo, shl, b1, wr ----
    {
        const uint4* ghi = (const uint4*)g_w1[branch][0];
        const uint4* glo = (const uint4*)g_w1[branch][1];
        uint4* shi = (uint4*)sw1hi;
        uint4* slo = (uint4*)sw1lo;
        for (int i = t; i < 1088; i += 128) { shi[i] = ghi[i]; slo[i] = glo[i]; }
    }
    ((float4*)shl)[t] = ((const float4*)(g_hl + (size_t)l0 * H0))[t];
    if (t < H1) { sb1[t] = b1[t]; swr[t] = Wr[t]; }

    const float* shl_l = shl + wid * H0;
    const float brv = br[0];

    const int kq = (lane & 3) * 2;
    const int rq = lane >> 2;

    for (int riter = 0; riter < 4; riter++) {
        const int rbase = rblk + riter * 32;

        // ---- stage shr [32][136] ----
        __syncthreads();
        for (int i = t; i < 1024; i += 128) {
            int row = i >> 5, c4 = i & 31;
            float4 v = ((const float4*)(g_hr + (size_t)(rbase + row) * H0))[c4];
            *(float4*)(shr + row * 136 + c4 * 4) = v;
        }
        __syncthreads();

        float acc[2][8][4];
#pragma unroll
        for (int mh = 0; mh < 2; mh++)
#pragma unroll
            for (int nt = 0; nt < 8; nt++)
#pragma unroll
                for (int c = 0; c < 4; c++) acc[mh][nt][c] = 0.0f;

#pragma unroll
        for (int kt = 0; kt < 8; kt++) {
            const int kk = kt * 16 + kq;

            // ---- A fragments (2 m16 halves, hi+lo) ----
            uint32_t ahi[2][4], alo[2][4];
            float2 y0 = *(const float2*)(shl_l + kk);
            float2 y1 = *(const float2*)(shl_l + kk + 8);
#pragma unroll
            for (int mh = 0; mh < 2; mh++) {
                int r_lo = mh * 16 + rq;
                const float* p0 = shr + r_lo * 136 + kk;
                const float* p1 = shr + (r_lo + 8) * 136 + kk;
                float2 x00 = *(const float2*)p0;
                float2 x01 = *(const float2*)(p0 + 8);
                float2 x10 = *(const float2*)p1;
                float2 x11 = *(const float2*)(p1 + 8);
                split2(fmaxf(x00.x + y0.x, 0.f), fmaxf(x00.y + y0.y, 0.f),
                       ahi[mh][0], alo[mh][0]);
                split2(fmaxf(x10.x + y0.x, 0.f), fmaxf(x10.y + y0.y, 0.f),
                       ahi[mh][1], alo[mh][1]);
                split2(fmaxf(x01.x + y1.x, 0.f), fmaxf(x01.y + y1.y, 0.f),
                       ahi[mh][2], alo[mh][2]);
                split2(fmaxf(x11.x + y1.x, 0.f), fmaxf(x11.y + y1.y, 0.f),
                       ahi[mh][3], alo[mh][3]);
            }

            // ---- B per nt (low register pressure), 6 MMAs per 4 LDS ----
#pragma unroll
            for (int nt = 0; nt < 8; nt++) {
                int w0 = (nt * 8 + rq) * 68 + kt * 8 + (lane & 3);
                uint32_t bh0 = w1hi32[w0], bh1 = w1hi32[w0 + 4];
                uint32_t bl0 = w1lo32[w0], bl1 = w1lo32[w0 + 4];
#pragma unroll
                for (int mh = 0; mh < 2; mh++) {
                    mma_bf16(acc[mh][nt][0], acc[mh][nt][1],
                             acc[mh][nt][2], acc[mh][nt][3],
                             ahi[mh][0], ahi[mh][1], ahi[mh][2], ahi[mh][3],
                             bh0, bh1);
                    mma_bf16(acc[mh][nt][0], acc[mh][nt][1],
                             acc[mh][nt][2], acc[mh][nt][3],
                             ahi[mh][0], ahi[mh][1], ahi[mh][2], ahi[mh][3],
                             bl0, bl1);
                    mma_bf16(acc[mh][nt][0], acc[mh][nt][1],
                             acc[mh][nt][2], acc[mh][nt][3],
                             alo[mh][0], alo[mh][1], alo[mh][2], alo[mh][3],
                             bh0, bh1);
                }
            }
        }

        // ---- epilogue: layer-2 relu/dot(Wr), quad reduce, ELU, store ----
#pragma unroll
        for (int mh = 0; mh < 2; mh++) {
            float s0 = 0.0f, s1 = 0.0f;
#pragma unroll
            for (int nt = 0; nt < 8; nt++) {
                int j0 = nt * 8 + kq;
                float bb0 = sb1[j0], bb1 = sb1[j0 + 1];
                float ww0 = swr[j0], ww1 = swr[j0 + 1];
                s0 = fmaf(fmaxf(acc[mh][nt][0] + bb0, 0.f), ww0, s0);
                s0 = fmaf(fmaxf(acc[mh][nt][1] + bb1, 0.f), ww1, s0);
                s1 = fmaf(fmaxf(acc[mh][nt][2] + bb0, 0.f), ww0, s1);
                s1 = fmaf(fmaxf(acc[mh][nt][3] + bb1, 0.f), ww1, s1);
            }
            s0 += __shfl_xor_sync(0xffffffffu, s0, 1);
            s0 += __shfl_xor_sync(0xffffffffu, s0, 2);
            s1 += __shfl_xor_sync(0xffffffffu, s1, 1);
            s1 += __shfl_xor_sync(0xffffffffu, s1, 2);
            if ((lane & 3) == 0) {
                int r_lo = rbase + mh * 16 + rq;
                float x0 = s0 + brv;
                float x1 = s1 + brv;
                float e0 = (x0 > 0.0f) ? x0 : expm1f(x0);
                float e1 = (x1 > 0.0f) ? x1 : expm1f(x1);
                float* arow = A + (size_t)(l0 + wid) * R;
                arow[r_lo]     = e0;
                arow[r_lo + 8] = e1;
            }
        }
    }
}

// ---------------------------------------------------------------------------
// Kernel 3: C = sigmoid(A @ B) via bf16 3-product MMA.
// CTA 256 thr (8 warps), C tile 128x128, warp tile 32m x 64n, k-chunk 32.
// smem: Ahi/Alo [128][42] bf16, Bhi/Blo [128 n][42 k] bf16 (B transposed).
// ---------------------------------------------------------------------------
#define GS_A_HI 0
#define GS_A_LO 10752
#define GS_B_HI 21504
#define GS_B_LO 32256
#define SMEM_GEMM 43008

__global__ __launch_bounds__(256, 2) void gemm_sigmoid_tc(
    const float* __restrict__ A, const float* __restrict__ B,
    float* __restrict__ C, int M, int N, int K)
{
    extern __shared__ char smem[];
    __nv_bfloat16* sAhi = (__nv_bfloat16*)(smem + GS_A_HI);
    __nv_bfloat16* sAlo = (__nv_bfloat16*)(smem + GS_A_LO);
    __nv_bfloat16* sBhi = (__nv_bfloat16*)(smem + GS_B_HI);
    __nv_bfloat16* sBlo = (__nv_bfloat16*)(smem + GS_B_LO);

    const int t    = threadIdx.x;
    const int wid  = t >> 5;
    const int lane = t & 31;
    const int m0 = blockIdx.y * 128, n0 = blockIdx.x * 128;
    const int wm = (wid >> 1) * 32;        // warp m offset (4 rows of warps)
    const int wn = (wid & 1) * 64;         // warp n offset
    const int kq = (lane & 3) * 2;
    const int rq = lane >> 2;

    float acc[2][8][4];
#pragma unroll
    for (int mh = 0; mh < 2; mh++)
#pragma unroll
        for (int nt = 0; nt < 8; nt++)
#pragma unroll
            for (int c = 0; c < 4; c++) acc[mh][nt][c] = 0.0f;

    for (int kb = 0; kb < K; kb += 32) {
        __syncthreads();
        // stage A [128 m][32 k] -> hi/lo bf16, row stride 42
#pragma unroll
        for (int i = t; i < 1024; i += 256) {
            int r = i >> 3, c4 = (i & 7) * 4;
            float4 v = *(const float4*)&A[(size_t)(m0 + r) * K + kb + c4];
            uint32_t h0, l0, h1, l1;
            split2(v.x, v.y, h0, l0);
            split2(v.z, v.w, h1, l1);
            uint32_t* dh = (uint32_t*)&sAhi[r * 42 + c4];
            uint32_t* dl = (uint32_t*)&sAlo[r * 42 + c4];
            dh[0] = h0; dh[1] = h1;
            dl[0] = l0; dl[1] = l1;
        }
        // stage B [32 k][128 n] -> transposed [n][k] hi/lo, row stride 42
#pragma unroll
        for (int i = t; i < 1024; i += 256) {
            int r = i >> 5, n4 = (i & 31) * 4;
            float4 v = *(const float4*)&B[(size_t)(kb + r) * N + n0 + n4];
            float f[4] = { v.x, v.y, v.z, v.w };
#pragma unroll
            for (int j = 0; j < 4; j++) {
                __nv_bfloat16 h = __float2bfloat16(f[j]);
                __nv_bfloat16 l = __float2bfloat16(f[j] - __bfloat162float(h));
                sBhi[(n4 + j) * 42 + r] = h;
                sBlo[(n4 + j) * 42 + r] = l;
            }
        }
        __syncthreads();

#pragma unroll
        for (int kt = 0; kt < 2; kt++) {
            const int kk = kt * 16 + kq;
            uint32_t ahi[2][4], alo[2][4];
#pragma unroll
            for (int mh = 0; mh < 2; mh++) {
                int mrow = wm + mh * 16 + rq;
                ahi[mh][0] = *(const uint32_t*)&sAhi[mrow * 42 + kk];
                ahi[mh][1] = *(const uint32_t*)&sAhi[(mrow + 8) * 42 + kk];
                ahi[mh][2] = *(const uint32_t*)&sAhi[mrow * 42 + kk + 8];
                ahi[mh][3] = *(const uint32_t*)&sAhi[(mrow + 8) * 42 + kk + 8];
                alo[mh][0] = *(const uint32_t*)&sAlo[mrow * 42 + kk];
                alo[mh][1] = *(const uint32_t*)&sAlo[(mrow + 8) * 42 + kk];
                alo[mh][2] = *(const uint32_t*)&sAlo[mrow * 42 + kk + 8];
                alo[mh][3] = *(const uint32_t*)&sAlo[(mrow + 8) * 42 + kk + 8];
            }
#pragma unroll
            for (int nt = 0; nt < 8; nt++) {
                int nrow = wn + nt * 8 + rq;
                uint32_t bh0 = *(const uint32_t*)&sBhi[nrow * 42 + kk];
                uint32_t bh1 = *(const uint32_t*)&sBhi[nrow * 42 + kk + 8];
                uint32_t bl0 = *(const uint32_t*)&sBlo[nrow * 42 + kk];
                uint32_t bl1 = *(const uint32_t*)&sBlo[nrow * 42 + kk + 8];
#pragma unroll
                for (int mh = 0; mh < 2; mh++) {
                    mma_bf16(acc[mh][nt][0], acc[mh][nt][1],
                             acc[mh][nt][2], acc[mh][nt][3],
                             ahi[mh][0], ahi[mh][1], ahi[mh][2], ahi[mh][3],
                             bh0, bh1);
                    mma_bf16(acc[mh][nt][0], acc[mh][nt][1],
                             acc[mh][nt][2], acc[mh][nt][3],
                             ahi[mh][0], ahi[mh][1], ahi[mh][2], ahi[mh][3],
                             bl0, bl1);
                    mma_bf16(acc[mh][nt][0], acc[mh][nt][1],
                             acc[mh][nt][2], acc[mh][nt][3],
                             alo[mh][0], alo[mh][1], alo[mh][2], alo[mh][3],
                             bh0, bh1);
                }
            }
        }
    }

    // epilogue: sigmoid, store
#pragma unroll
    for (int mh = 0; mh < 2; mh++)
#pragma unroll
        for (int nt = 0; nt < 8; nt++) {
            int row = m0 + wm + mh * 16 + rq;
            int col = n0 + wn + nt * 8 + kq;
            float v0 = acc[mh][nt][0], v1 = acc[mh][nt][1];
            float v2 = acc[mh][nt][2], v3 = acc[mh][nt][3];
            float* r0p = &C[(size_t)row * N + col];
            float* r1p = &C[(size_t)(row + 8) * N + col];
            r0p[0] = 1.0f / (1.0f + expf(-v0));
            r0p[1] = 1.0f / (1.0f + expf(-v1));
            r1p[0] = 1.0f / (1.0f + expf(-v2));
            r1p[1] = 1.0f / (1.0f + expf(-v3));
        }
}

// ---------------------------------------------------------------------------
// Launch
// ---------------------------------------------------------------------------
extern "C" void kernel_launch(void* const* d_in, const int* in_sizes, int n_in,
                              void* d_out, int out_size)
{
    const float* X_ch   = (const float*)d_in[0];
    const float* X_g    = (const float*)d_in[1];
    const float* X_d    = (const float*)d_in[2];
    const float* W_chg0 = (const float*)d_in[3];
    const float* b_chg0 = (const float*)d_in[4];
    const float* W_chg1 = (const float*)d_in[5];
    const float* b_chg1 = (const float*)d_in[6];
    const float* W_chgr = (const float*)d_in[7];
    const float* b_chgr = (const float*)d_in[8];
    const float* W_dg0  = (const float*)d_in[9];
    const float* b_dg0  = (const float*)d_in[10];
    const float* W_dg1  = (const float*)d_in[11];
    const float* b_dg1  = (const float*)d_in[12];
    const float* W_dgr  = (const float*)d_in[13];
    const float* b_dgr  = (const float*)d_in[14];

    int Nch = in_sizes[0] / D_IN;
    int Ng  = in_sizes[1] / D_IN;
    int Nd  = in_sizes[2] / D_IN;

    float* out   = (float*)d_out;
    float* A_chg = out + (size_t)Nch * Nd;
    float* A_gd  = A_chg + (size_t)Nch * Ng;

    int maxN = Nch > Ng ? Nch : Ng; if (Nd > maxN) maxN = Nd;
    precompute_kernel<<<dim3(maxN, 4), 128>>>(
        X_ch, X_g, X_d, W_chg0, b_chg0, W_dg0, b_dg0, Nch, Ng, Nd);
    w1split_kernel<<<2, 256>>>(W_chg1, W_dg1);

    cudaFuncSetAttribute(pair_mlp_mma,
                         cudaFuncAttributeMaxDynamicSharedMemorySize, SMEM_PAIR);
    cudaFuncSetAttribute(gemm_sigmoid_tc,
                         cudaFuncAttributeMaxDynamicSharedMemorySize, SMEM_GEMM);

    // both pair-MLP branches in one grid (Nch==Ng==Nd assumed square here)
    pair_mlp_mma<<<dim3(Ng / 128, Nch / 4, 2), 128, SMEM_PAIR>>>(
        b_chg1, W_chgr, b_chgr, A_chg,
        b_dg1,  W_dgr,  b_dgr,  A_gd, Ng);

    gemm_sigmoid_tc<<<dim3(Nd / 128, Nch / 128), 256, SMEM_GEMM>>>(
        A_chg, A_gd, out, Nch, Nd, Ng);
}

// round 6
// speedup vs baseline: 3.7449x; 1.2173x over previous
#include <cuda_runtime.h>
#include <cuda_bf16.h>
#include <math.h>
#include <stdint.h>

#define D_IN 5
#define H0 128
#define H1 64

// scratch: 4 arrays of [1024][128] fp32 (hl_chg, hr_chg, hl_dg, hr_dg)
__device__ float g_hbuf[4 * 1024 * 128];
// W1 hi/lo bf16, n-major padded: [branch][hi/lo][64 rows][136 cols]
__device__ __align__(16) __nv_bfloat16 g_w1[2][2][64 * 136];
// pre-split gemm operands: [op A/B][hi/lo][1024*1024] bf16
// opA = A_chg in [m][k]; opB = A_gd in [k][n]
__device__ __align__(16) __nv_bfloat16 g_ops[2][2][1024 * 1024];

// ---------------------------------------------------------------------------
// PTX helpers (all architecture-portable: sm_80-level)
// ---------------------------------------------------------------------------
__device__ __forceinline__ void mma_bf16(
    float& d0, float& d1, float& d2, float& d3,
    uint32_t a0, uint32_t a1, uint32_t a2, uint32_t a3,
    uint32_t b0, uint32_t b1)
{
    asm volatile(
        "mma.sync.aligned.m16n8k16.row.col.f32.bf16.bf16.f32 "
        "{%0,%1,%2,%3}, {%4,%5,%6,%7}, {%8,%9}, {%0,%1,%2,%3};"
        : "+f"(d0), "+f"(d1), "+f"(d2), "+f"(d3)
        : "r"(a0), "r"(a1), "r"(a2), "r"(a3), "r"(b0), "r"(b1));
}

__device__ __forceinline__ void split2(float a, float b, uint32_t& hi, uint32_t& lo) {
    __nv_bfloat162 h = __float22bfloat162_rn(make_float2(a, b));
    float ra = a - __bfloat162float(h.x);
    float rb = b - __bfloat162float(h.y);
    __nv_bfloat162 l = __float22bfloat162_rn(make_float2(ra, rb));
    hi = *reinterpret_cast<uint32_t*>(&h);
    lo = *reinterpret_cast<uint32_t*>(&l);
}

__device__ __forceinline__ uint32_t smem_u32(const void* p) {
    uint32_t a;
    asm("{ .reg .u64 t; cvta.to.shared.u64 t, %1; cvt.u32.u64 %0, t; }"
        : "=r"(a) : "l"(p));
    return a;
}
__device__ __forceinline__ void cp_async16(uint32_t dst, const void* src) {
    asm volatile("cp.async.cg.shared.global [%0], [%1], 16;"
                 :: "r"(dst), "l"(src));
}
#define CP_COMMIT() asm volatile("cp.async.commit_group;" ::: "memory")
#define CP_WAIT(n)  asm volatile("cp.async.wait_group %0;" :: "n"(n) : "memory")

__device__ __forceinline__ void ldsm_x4(uint32_t& r0, uint32_t& r1,
                                        uint32_t& r2, uint32_t& r3, uint32_t a) {
    asm volatile("ldmatrix.sync.aligned.m8n8.x4.shared.b16 {%0,%1,%2,%3}, [%4];"
                 : "=r"(r0), "=r"(r1), "=r"(r2), "=r"(r3) : "r"(a));
}
__device__ __forceinline__ void ldsm_x4t(uint32_t& r0, uint32_t& r1,
                                         uint32_t& r2, uint32_t& r3, uint32_t a) {
    asm volatile("ldmatrix.sync.aligned.m8n8.x4.trans.shared.b16 {%0,%1,%2,%3}, [%4];"
                 : "=r"(r0), "=r"(r1), "=r"(r2), "=r"(r3) : "r"(a));
}
__device__ __forceinline__ uint32_t sw128(uint32_t bo) {
    return bo ^ ((bo >> 3) & 0x70);
}

// ---------------------------------------------------------------------------
// Kernel 1: precompute hl/hr for both branches (bias folded into hl)
// ---------------------------------------------------------------------------
__global__ void precompute_kernel(
    const float* __restrict__ X_ch, const float* __restrict__ X_g,
    const float* __restrict__ X_d,
    const float* __restrict__ W_chg0, const float* __restrict__ b_chg0,
    const float* __restrict__ W_dg0,  const float* __restrict__ b_dg0,
    int Nch, int Ng, int Nd)
{
    int a   = blockIdx.y;
    int row = blockIdx.x;
    int k   = threadIdx.x;

    const float* X; const float* W; const float* b = nullptr;
    int rows, woff;
    if (a == 0)      { X = X_ch; W = W_chg0; b = b_chg0; rows = Nch; woff = 0; }
    else if (a == 1) { X = X_g;  W = W_chg0;             rows = Ng;  woff = D_IN; }
    else if (a == 2) { X = X_g;  W = W_dg0;  b = b_dg0;  rows = Ng;  woff = 0; }
    else             { X = X_d;  W = W_dg0;              rows = Nd;  woff = D_IN; }
    if (row >= rows) return;

    float v = b ? b[k] : 0.0f;
#pragma unroll
    for (int d = 0; d < D_IN; d++)
        v = fmaf(X[row * D_IN + d], W[(woff + d) * H0 + k], v);
    g_hbuf[(a * 1024 + row) * H0 + k] = v;
}

// ---------------------------------------------------------------------------
// Kernel 1b: split W1 (both branches) into bf16 hi/lo, n-major padded [64][136]
// ---------------------------------------------------------------------------
__global__ void w1split_kernel(const float* __restrict__ W1a,
                               const float* __restrict__ W1b)
{
    int br = blockIdx.x;
    const float* W = br ? W1b : W1a;
    for (int i = threadIdx.x; i < 64 * 136; i += blockDim.x) {
        int n = i / 136, k = i % 136;
        float v = (k < H0) ? W[k * H1 + n] : 0.0f;
        __nv_bfloat16 h = __float2bfloat16(v);
        __nv_bfloat16 l = __float2bfloat16(v - __bfloat162float(h));
        g_w1[br][0][i] = h;
        g_w1[br][1][i] = l;
    }
}

// ---------------------------------------------------------------------------
// Kernel 2: pair MLP with warp-level bf16 MMA (3-product split), both branches
// in one grid (blockIdx.z). Epilogue also emits bf16 hi/lo of the result into
// g_ops (opA = A_chg [m][k], opB = A_gd [k][n] — both the natural layout).
// ---------------------------------------------------------------------------
#define SMEM_PAIR 54784

__global__ __launch_bounds__(128, 4) void pair_mlp_mma(
    const float* __restrict__ b1a, const float* __restrict__ Wra,
    const float* __restrict__ bra, float* __restrict__ Aa,
    const float* __restrict__ b1b, const float* __restrict__ Wrb,
    const float* __restrict__ brb, float* __restrict__ Ab,
    int R)
{
    extern __shared__ char smem[];
    __nv_bfloat16* sw1hi = (__nv_bfloat16*)smem;
    __nv_bfloat16* sw1lo = (__nv_bfloat16*)(smem + 17408);
    float* shr = (float*)(smem + 34816);
    float* shl = (float*)(smem + 52224);
    float* sb1 = (float*)(smem + 54272);
    float* swr = (float*)(smem + 54528);
    const uint32_t* w1hi32 = (const uint32_t*)sw1hi;
    const uint32_t* w1lo32 = (const uint32_t*)sw1lo;

    const int branch = blockIdx.z;
    const float* g_hl = g_hbuf + (branch ? 2 : 0) * 1024 * H0;
    const float* g_hr = g_hbuf + (branch ? 3 : 1) * 1024 * H0;
    const float* b1 = branch ? b1b : b1a;
    const float* Wr = branch ? Wrb : Wra;
    const float* br = branch ? brb : bra;
    float* A = branch ? Ab : Aa;
    __nv_bfloat16* opHi = g_ops[branch][0];
    __nv_bfloat16* opLo = g_ops[branch][1];

    const int t    = threadIdx.x;
    const int wid  = t >> 5;
    const int lane = t & 31;
    const int l0   = blockIdx.y * 4;
    const int rblk = blockIdx.x * 128;

    {
        const uint4* ghi = (const uint4*)g_w1[branch][0];
        const uint4* glo = (const uint4*)g_w1[branch][1];
        uint4* shi = (uint4*)sw1hi;
        uint4* slo = (uint4*)sw1lo;
        for (int i = t; i < 1088; i += 128) { shi[i] = ghi[i]; slo[i] = glo[i]; }
    }
    ((float4*)shl)[t] = ((const float4*)(g_hl + (size_t)l0 * H0))[t];
    if (t < H1) { sb1[t] = b1[t]; swr[t] = Wr[t]; }

    const float* shl_l = shl + wid * H0;
    const float brv = br[0];

    const int kq = (lane & 3) * 2;
    const int rq = lane >> 2;

    for (int riter = 0; riter < 4; riter++) {
        const int rbase = rblk + riter * 32;

        __syncthreads();
        for (int i = t; i < 1024; i += 128) {
            int row = i >> 5, c4 = i & 31;
            float4 v = ((const float4*)(g_hr + (size_t)(rbase + row) * H0))[c4];
            *(float4*)(shr + row * 136 + c4 * 4) = v;
        }
        __syncthreads();

        float acc[2][8][4];
#pragma unroll
        for (int mh = 0; mh < 2; mh++)
#pragma unroll
            for (int nt = 0; nt < 8; nt++)
#pragma unroll
                for (int c = 0; c < 4; c++) acc[mh][nt][c] = 0.0f;

#pragma unroll
        for (int kt = 0; kt < 8; kt++) {
            const int kk = kt * 16 + kq;

            uint32_t ahi[2][4], alo[2][4];
            float2 y0 = *(const float2*)(shl_l + kk);
            float2 y1 = *(const float2*)(shl_l + kk + 8);
#pragma unroll
            for (int mh = 0; mh < 2; mh++) {
                int r_lo = mh * 16 + rq;
                const float* p0 = shr + r_lo * 136 + kk;
                const float* p1 = shr + (r_lo + 8) * 136 + kk;
                float2 x00 = *(const float2*)p0;
                float2 x01 = *(const float2*)(p0 + 8);
                float2 x10 = *(const float2*)p1;
                float2 x11 = *(const float2*)(p1 + 8);
                split2(fmaxf(x00.x + y0.x, 0.f), fmaxf(x00.y + y0.y, 0.f),
                       ahi[mh][0], alo[mh][0]);
                split2(fmaxf(x10.x + y0.x, 0.f), fmaxf(x10.y + y0.y, 0.f),
                       ahi[mh][1], alo[mh][1]);
                split2(fmaxf(x01.x + y1.x, 0.f), fmaxf(x01.y + y1.y, 0.f),
                       ahi[mh][2], alo[mh][2]);
                split2(fmaxf(x11.x + y1.x, 0.f), fmaxf(x11.y + y1.y, 0.f),
                       ahi[mh][3], alo[mh][3]);
            }

#pragma unroll
            for (int nt = 0; nt < 8; nt++) {
                int w0 = (nt * 8 + rq) * 68 + kt * 8 + (lane & 3);
                uint32_t bh0 = w1hi32[w0], bh1 = w1hi32[w0 + 4];
                uint32_t bl0 = w1lo32[w0], bl1 = w1lo32[w0 + 4];
#pragma unroll
                for (int mh = 0; mh < 2; mh++) {
                    mma_bf16(acc[mh][nt][0], acc[mh][nt][1],
                             acc[mh][nt][2], acc[mh][nt][3],
                             ahi[mh][0], ahi[mh][1], ahi[mh][2], ahi[mh][3],
                             bh0, bh1);
                    mma_bf16(acc[mh][nt][0], acc[mh][nt][1],
                             acc[mh][nt][2], acc[mh][nt][3],
                             ahi[mh][0], ahi[mh][1], ahi[mh][2], ahi[mh][3],
                             bl0, bl1);
                    mma_bf16(acc[mh][nt][0], acc[mh][nt][1],
                             acc[mh][nt][2], acc[mh][nt][3],
                             alo[mh][0], alo[mh][1], alo[mh][2], alo[mh][3],
                             bh0, bh1);
                }
            }
        }

        // epilogue: layer-2 relu/dot(Wr), quad reduce, ELU, store (f32 + bf16 split)
#pragma unroll
        for (int mh = 0; mh < 2; mh++) {
            float s0 = 0.0f, s1 = 0.0f;
#pragma unroll
            for (int nt = 0; nt < 8; nt++) {
                int j0 = nt * 8 + kq;
                float bb0 = sb1[j0], bb1 = sb1[j0 + 1];
                float ww0 = swr[j0], ww1 = swr[j0 + 1];
                s0 = fmaf(fmaxf(acc[mh][nt][0] + bb0, 0.f), ww0, s0);
                s0 = fmaf(fmaxf(acc[mh][nt][1] + bb1, 0.f), ww1, s0);
                s1 = fmaf(fmaxf(acc[mh][nt][2] + bb0, 0.f), ww0, s1);
                s1 = fmaf(fmaxf(acc[mh][nt][3] + bb1, 0.f), ww1, s1);
            }
            s0 += __shfl_xor_sync(0xffffffffu, s0, 1);
            s0 += __shfl_xor_sync(0xffffffffu, s0, 2);
            s1 += __shfl_xor_sync(0xffffffffu, s1, 1);
            s1 += __shfl_xor_sync(0xffffffffu, s1, 2);
            if ((lane & 3) == 0) {
                int r_lo = rbase + mh * 16 + rq;
                float x0 = s0 + brv;
                float x1 = s1 + brv;
                float e0 = (x0 > 0.0f) ? x0 : expm1f(x0);
                float e1 = (x1 > 0.0f) ? x1 : expm1f(x1);
                size_t rowoff = (size_t)(l0 + wid) * R;
                float* arow = A + rowoff;
                arow[r_lo]     = e0;
                arow[r_lo + 8] = e1;
                __nv_bfloat16 h0 = __float2bfloat16(e0);
                __nv_bfloat16 h1 = __float2bfloat16(e1);
                opHi[rowoff + r_lo]     = h0;
                opHi[rowoff + r_lo + 8] = h1;
                opLo[rowoff + r_lo]     = __float2bfloat16(e0 - __bfloat162float(h0));
                opLo[rowoff + r_lo + 8] = __float2bfloat16(e1 - __bfloat162float(h1));
            }
        }
    }
}

// ---------------------------------------------------------------------------
// Kernel 3: C = sigmoid(A @ B), bf16 3-product MMA, operands pre-split.
// CTA: 128m x 64n, 8 warps (4m x 2n), warp tile 32m x 32n.
// k-chunks of 64, cp.async double buffer, ldmatrix(+trans) fragment loads,
// XOR-swizzled smem (128B rows).
// Stage layout (per buffer, 48KB): Ahi 16K | Alo 16K | Bhi 8K | Blo 8K
// ---------------------------------------------------------------------------
#define GS_STAGE 49152
#define GS_ALO   16384
#define GS_BHI   32768
#define GS_BLO   40960
#define SMEM_GEMM (2 * GS_STAGE)

__global__ __launch_bounds__(256, 1) void gemm_sigmoid_tc(
    float* __restrict__ C, int M, int N, int K)
{
    extern __shared__ char smem[];
    const uint32_t sb = smem_u32(smem);

    const __nv_bfloat16* gAhi = g_ops[0][0];
    const __nv_bfloat16* gAlo = g_ops[0][1];
    const __nv_bfloat16* gBhi = g_ops[1][0];
    const __nv_bfloat16* gBlo = g_ops[1][1];

    const int t    = threadIdx.x;
    const int wid  = t >> 5;
    const int lane = t & 31;
    const int m0 = blockIdx.y * 128, n0 = blockIdx.x * 64;
    const int wm = (wid >> 1) * 32;
    const int wn = (wid & 1) * 32;
    const int kq = (lane & 3) * 2;
    const int rq = lane >> 2;

    float acc[2][4][4];
#pragma unroll
    for (int mh = 0; mh < 2; mh++)
#pragma unroll
        for (int nt = 0; nt < 4; nt++)
#pragma unroll
            for (int c = 0; c < 4; c++) acc[mh][nt][c] = 0.0f;

    const int K64 = K >> 6;

    // stage chunk kb into buffer buf
    auto stage = [&](int kb, int buf) {
        uint32_t base = sb + buf * GS_STAGE;
#pragma unroll
        for (int i = t; i < 1024; i += 256) {
            int m = i >> 3, c = i & 7;
            uint32_t sw = sw128((uint32_t)(m * 128 + c * 16));
            size_t off = (size_t)(m0 + m) * K + kb * 64 + c * 8;
            cp_async16(base + sw, gAhi + off);
            cp_async16(base + GS_ALO + sw, gAlo + off);
        }
#pragma unroll
        for (int i = t; i < 512; i += 256) {
            int k = i >> 3, c = i & 7;
            uint32_t sw = sw128((uint32_t)(k * 128 + c * 16));
            size_t off = (size_t)(kb * 64 + k) * N + n0 + c * 8;
            cp_async16(base + GS_BHI + sw, gBhi + off);
            cp_async16(base + GS_BLO + sw, gBlo + off);
        }
    };

    stage(0, 0);
    CP_COMMIT();

    for (int kb = 0; kb < K64; kb++) {
        if (kb + 1 < K64) {
            stage(kb + 1, (kb + 1) & 1);
            CP_COMMIT();
            CP_WAIT(1);
        } else {
            CP_WAIT(0);
        }
        __syncthreads();

        uint32_t base = sb + (kb & 1) * GS_STAGE;
#pragma unroll
        for (int kt = 0; kt < 4; kt++) {
            // A fragments
            uint32_t ahi[2][4], alo[2][4];
#pragma unroll
            for (int mh = 0; mh < 2; mh++) {
                int row = wm + mh * 16 + (lane & 15);
                uint32_t sw = sw128((uint32_t)(row * 128 + kt * 32 + (lane >> 4) * 16));
                ldsm_x4(ahi[mh][0], ahi[mh][1], ahi[mh][2], ahi[mh][3], base + sw);
                ldsm_x4(alo[mh][0], alo[mh][1], alo[mh][2], alo[mh][3],
                        base + GS_ALO + sw);
            }
            // B fragments (transposed load from [k][n])
            uint32_t bh[4][2], bl[4][2];
#pragma unroll
            for (int np = 0; np < 2; np++) {
                int krow = kt * 16 + (lane & 15);
                uint32_t sw = sw128((uint32_t)(krow * 128 + wn * 2 + np * 32
                                               + (lane >> 4) * 16));
                uint32_t r0, r1, r2, r3;
                ldsm_x4t(r0, r1, r2, r3, base + GS_BHI + sw);
                bh[np * 2][0] = r0; bh[np * 2][1] = r1;
                bh[np * 2 + 1][0] = r2; bh[np * 2 + 1][1] = r3;
                ldsm_x4t(r0, r1, r2, r3, base + GS_BLO + sw);
                bl[np * 2][0] = r0; bl[np * 2][1] = r1;
                bl[np * 2 + 1][0] = r2; bl[np * 2 + 1][1] = r3;
            }
#pragma unroll
            for (int nt = 0; nt < 4; nt++)
#pragma unroll
                for (int mh = 0; mh < 2; mh++) {
                    mma_bf16(acc[mh][nt][0], acc[mh][nt][1],
                             acc[mh][nt][2], acc[mh][nt][3],
                             ahi[mh][0], ahi[mh][1], ahi[mh][2], ahi[mh][3],
                             bh[nt][0], bh[nt][1]);
                    mma_bf16(acc[mh][nt][0], acc[mh][nt][1],
                             acc[mh][nt][2], acc[mh][nt][3],
                             ahi[mh][0], ahi[mh][1], ahi[mh][2], ahi[mh][3],
                             bl[nt][0], bl[nt][1]);
                    mma_bf16(acc[mh][nt][0], acc[mh][nt][1],
                             acc[mh][nt][2], acc[mh][nt][3],
                             alo[mh][0], alo[mh][1], alo[mh][2], alo[mh][3],
                             bh[nt][0], bh[nt][1]);
                }
        }
        __syncthreads();
    }

    // epilogue: sigmoid, store
#pragma unroll
    for (int mh = 0; mh < 2; mh++)
#pragma unroll
        for (int nt = 0; nt < 4; nt++) {
            int row = m0 + wm + mh * 16 + rq;
            int col = n0 + wn + nt * 8 + kq;
            float* r0p = &C[(size_t)row * N + col];
            float* r1p = &C[(size_t)(row + 8) * N + col];
            r0p[0] = 1.0f / (1.0f + __expf(-acc[mh][nt][0]));
            r0p[1] = 1.0f / (1.0f + __expf(-acc[mh][nt][1]));
            r1p[0] = 1.0f / (1.0f + __expf(-acc[mh][nt][2]));
            r1p[1] = 1.0f / (1.0f + __expf(-acc[mh][nt][3]));
        }
}

// ---------------------------------------------------------------------------
// Launch
// ---------------------------------------------------------------------------
extern "C" void kernel_launch(void* const* d_in, const int* in_sizes, int n_in,
                              void* d_out, int out_size)
{
    const float* X_ch   = (const float*)d_in[0];
    const float* X_g    = (const float*)d_in[1];
    const float* X_d    = (const float*)d_in[2];
    const float* W_chg0 = (const float*)d_in[3];
    const float* b_chg0 = (const float*)d_in[4];
    const float* W_chg1 = (const float*)d_in[5];
    const float* b_chg1 = (const float*)d_in[6];
    const float* W_chgr = (const float*)d_in[7];
    const float* b_chgr = (const float*)d_in[8];
    const float* W_dg0  = (const float*)d_in[9];
    const float* b_dg0  = (const float*)d_in[10];
    const float* W_dg1  = (const float*)d_in[11];
    const float* b_dg1  = (const float*)d_in[12];
    const float* W_dgr  = (const float*)d_in[13];
    const float* b_dgr  = (const float*)d_in[14];

    int Nch = in_sizes[0] / D_IN;
    int Ng  = in_sizes[1] / D_IN;
    int Nd  = in_sizes[2] / D_IN;

    float* out   = (float*)d_out;
    float* A_chg = out + (size_t)Nch * Nd;
    float* A_gd  = A_chg + (size_t)Nch * Ng;

    int maxN = Nch > Ng ? Nch : Ng; if (Nd > maxN) maxN = Nd;
    precompute_kernel<<<dim3(maxN, 4), 128>>>(
        X_ch, X_g, X_d, W_chg0, b_chg0, W_dg0, b_dg0, Nch, Ng, Nd);
    w1split_kernel<<<2, 256>>>(W_chg1, W_dg1);

    cudaFuncSetAttribute(pair_mlp_mma,
                         cudaFuncAttributeMaxDynamicSharedMemorySize, SMEM_PAIR);
    cudaFuncSetAttribute(gemm_sigmoid_tc,
                         cudaFuncAttributeMaxDynamicSharedMemorySize, SMEM_GEMM);

    pair_mlp_mma<<<dim3(Ng / 128, Nch / 4, 2), 128, SMEM_PAIR>>>(
        b_chg1, W_chgr, b_chgr, A_chg,
        b_dg1,  W_dgr,  b_dgr,  A_gd, Ng);

    gemm_sigmoid_tc<<<dim3(Nd / 64, Nch / 128), 256, SMEM_GEMM>>>(
        out, Nch, Nd, Ng);
}